// round 14
// baseline (speedup 1.0000x reference)
#include <cuda_runtime.h>
#include <cuda_fp16.h>
#include <cstdint>

#define NMAX 50000
#define EMAX 800000
#define F 512
#define H 128

// ---- scratch (static device globals: no allocation allowed) ----
__device__ __half   g_x[(size_t)NMAX * H];     // (h @ W) * out_norm, fp16
__device__ int      g_deg_out[NMAX];
__device__ int      g_deg_in[NMAX];
__device__ int      g_off[NMAX];               // CSR offsets (by dst)
__device__ int      g_cursor[NMAX];            // fill cursors
__device__ int      g_esrc[EMAX];              // src ids grouped by dst
__device__ int      g_base_ctr;                // scan block-base counter
__device__ uint16_t g_Wh[(size_t)H * F];       // fp16 W^T: [n][k]

// ---- zero degrees + counter + W fp16 transpose (graph replays) ----
__global__ void zero_kernel(const float* __restrict__ W, int n) {
    int i = blockIdx.x * blockDim.x + threadIdx.x;
    if (i == 0) g_base_ctr = 0;
    if (i < n) { g_deg_out[i] = 0; g_deg_in[i] = 0; }
    if (i < H * F) {
        int nn = i >> 9;        // 0..127
        int k  = i & (F - 1);   // 0..511
        __half hv = __float2half_rn(W[(size_t)k * H + nn]);
        g_Wh[i] = *reinterpret_cast<uint16_t*>(&hv);
    }
}

// ---- degree histograms (int4 vectorized) ----
__global__ void deg_kernel(const int* __restrict__ src,
                           const int* __restrict__ dst, int e) {
    int i4 = (blockIdx.x * blockDim.x + threadIdx.x) * 4;
    if (i4 + 3 < e) {
        int4 s = *reinterpret_cast<const int4*>(&src[i4]);
        int4 d = *reinterpret_cast<const int4*>(&dst[i4]);
        atomicAdd(&g_deg_out[s.x], 1); atomicAdd(&g_deg_out[s.y], 1);
        atomicAdd(&g_deg_out[s.z], 1); atomicAdd(&g_deg_out[s.w], 1);
        atomicAdd(&g_deg_in[d.x], 1);  atomicAdd(&g_deg_in[d.y], 1);
        atomicAdd(&g_deg_in[d.z], 1);  atomicAdd(&g_deg_in[d.w], 1);
    } else {
        for (int i = i4; i < e; i++) {
            atomicAdd(&g_deg_out[src[i]], 1);
            atomicAdd(&g_deg_in[dst[i]], 1);
        }
    }
}

// ---- parallel exclusive scan v2: shfl warp scan, 2 barriers ----
__global__ __launch_bounds__(256) void scan_kernel(int n) {
    __shared__ int wsum[8];
    __shared__ int base;
    const int t = threadIdx.x;
    const int lane = t & 31;
    const int w = t >> 5;
    const int i = blockIdx.x * 256 + t;
    int d = (i < n) ? g_deg_in[i] : 0;

    // inclusive warp scan of d
    int x = d;
#pragma unroll
    for (int off = 1; off < 32; off <<= 1) {
        int v = __shfl_up_sync(0xffffffffu, x, off);
        if (lane >= off) x += v;
    }
    if (lane == 31) wsum[w] = x;
    __syncthreads();
    if (w == 0) {
        int v = (lane < 8) ? wsum[lane] : 0;
#pragma unroll
        for (int off = 1; off < 8; off <<= 1) {
            int u = __shfl_up_sync(0xffffffffu, v, off);
            if (lane >= off) v += u;
        }
        if (lane < 8) wsum[lane] = v;                 // inclusive warp totals
        if (lane == 7) base = atomicAdd(&g_base_ctr, v);  // block total
    }
    __syncthreads();
    if (i < n) {
        int o = base + (w ? wsum[w - 1] : 0) + x - d;  // exclusive
        g_off[i] = o;
        g_cursor[i] = o;
    }
}

// ---- CSR fill: group edge sources by destination (int4 vectorized) ----
__global__ void fill_kernel(const int* __restrict__ src,
                            const int* __restrict__ dst, int e) {
    int i4 = (blockIdx.x * blockDim.x + threadIdx.x) * 4;
    if (i4 + 3 < e) {
        int4 s = *reinterpret_cast<const int4*>(&src[i4]);
        int4 d = *reinterpret_cast<const int4*>(&dst[i4]);
        g_esrc[atomicAdd(&g_cursor[d.x], 1)] = s.x;
        g_esrc[atomicAdd(&g_cursor[d.y], 1)] = s.y;
        g_esrc[atomicAdd(&g_cursor[d.z], 1)] = s.z;
        g_esrc[atomicAdd(&g_cursor[d.w], 1)] = s.w;
    } else {
        for (int i = i4; i < e; i++)
            g_esrc[atomicAdd(&g_cursor[dst[i]], 1)] = src[i];
    }
}

// ============================================================
// Tensor-core GEMM v6 (measured 43.6us): single fp16 term,
// row-scale in epilogue:
//   g_x = (h @ W) * out_norm[:,None]   (out_norm = rsqrt(deg_out))
// CTA tile 64(m) x 128(n); 256 threads: 8 warps as 2(m) x 4(n),
// warp tile 32x32, 32 accum regs/thread -> 3 CTAs/SM.
// KT=32, double-buffered; register-staged A (one smem trip for A).
// ============================================================
#define KT 32
#define LDP 40   // padded row length in halves (80B stride, ldmatrix-clean)
#define A_STG (64 * LDP)
#define B_STG (128 * LDP)

#define SA(st)  ((st) * A_STG)
#define SBH(st) (2 * A_STG + (st) * B_STG)
#define SM_HALVES (2 * A_STG + 2 * B_STG)
#define SM_BYTES (SM_HALVES * 2)   // 30720

#define MMA_F16(D, A, B0, B1)                                                \
    asm volatile(                                                            \
        "mma.sync.aligned.m16n8k16.row.col.f32.f16.f16.f32 "                 \
        "{%0,%1,%2,%3}, {%4,%5,%6,%7}, {%8,%9}, {%0,%1,%2,%3};"              \
        : "+f"((D)[0]), "+f"((D)[1]), "+f"((D)[2]), "+f"((D)[3])             \
        : "r"((A)[0]), "r"((A)[1]), "r"((A)[2]), "r"((A)[3]),                \
          "r"(B0), "r"(B1))

#define LDMX4(R, PTR)                                                        \
    do {                                                                     \
        uint32_t _a = (uint32_t)__cvta_generic_to_shared(PTR);               \
        asm volatile(                                                        \
            "ldmatrix.sync.aligned.m8n8.x4.shared.b16 {%0,%1,%2,%3}, [%4];"  \
            : "=r"((R)[0]), "=r"((R)[1]), "=r"((R)[2]), "=r"((R)[3])         \
            : "r"(_a));                                                      \
    } while (0)

#define CPA16(DST_PTR, SRC_PTR)                                              \
    do {                                                                     \
        uint32_t _d = (uint32_t)__cvta_generic_to_shared(DST_PTR);           \
        asm volatile("cp.async.cg.shared.global [%0], [%1], 16;"             \
                     :: "r"(_d), "l"(SRC_PTR));                              \
    } while (0)

__global__ __launch_bounds__(256, 3) void gemm_mma_kernel(
    const float* __restrict__ hin, int n) {
    extern __shared__ uint16_t sm[];
    const int tid = threadIdx.x;
    const int wid = tid >> 5;
    const int lid = tid & 31;
    const int g = lid >> 2;          // groupID
    const int t = lid & 3;           // threadID_in_group
    const int wm = (wid & 1) * 32;   // warp row base (2 m-tiles)
    const int wn = (wid >> 1) * 32;  // warp col base (4 n-tiles)
    const int brow = blockIdx.x * 64;
    // ldmatrix lane -> (row offset, col offset) within a 16x16 tile
    const int ro = ((lid >> 3) & 1) * 8 + (lid & 7);
    const int co = (lid >> 4) * 8;

    float d[2][4][4];
#pragma unroll
    for (int mf = 0; mf < 2; mf++)
#pragma unroll
        for (int nf = 0; nf < 4; nf++)
#pragma unroll
            for (int q = 0; q < 4; q++) d[mf][nf][q] = 0.f;

    // A mapping: row = tid/4 (0..63), 8 fp32 per thread per 32-chunk
    const int arow  = tid >> 2;
    const int acol  = (tid & 3) * 8;
    const int agrow = brow + arow;
    const bool a_ok = agrow < n;
    // B mapping: n-row = tid/2 (0..127), 16-half segment per thread
    const int bn   = tid >> 1;
    const int bseg = (tid & 1) * 16;

    float4 areg[2];
    // prologue: stage A chunk 0 into registers, cp.async B chunk 0 -> stage 0
#pragma unroll
    for (int i = 0; i < 2; i++)
        areg[i] = a_ok ? *reinterpret_cast<const float4*>(
                             &hin[(size_t)agrow * F + acol + i * 4])
                       : make_float4(0.f, 0.f, 0.f, 0.f);
    CPA16(&sm[SBH(0) + bn * LDP + bseg],     &g_Wh[(size_t)bn * F + bseg]);
    CPA16(&sm[SBH(0) + bn * LDP + bseg + 8], &g_Wh[(size_t)bn * F + bseg + 8]);
    asm volatile("cp.async.commit_group;");

    for (int c = 0; c < F / KT; c++) {
        const int st = c & 1;

        // convert staged raw-h registers -> fp16 smem (stage st)
#pragma unroll
        for (int i = 0; i < 2; i++) {
            __half2 p01 = __float22half2_rn(make_float2(areg[i].x, areg[i].y));
            __half2 p23 = __float22half2_rn(make_float2(areg[i].z, areg[i].w));
            uint2 hp;
            hp.x = *reinterpret_cast<uint32_t*>(&p01);
            hp.y = *reinterpret_cast<uint32_t*>(&p23);
            *reinterpret_cast<uint2*>(
                &sm[SA(st) + arow * LDP + acol + i * 4]) = hp;
        }
        // stage A chunk c+1 into registers (overlaps MMA below)
        if (c < F / KT - 1) {
            const int k1 = (c + 1) * KT;
#pragma unroll
            for (int i = 0; i < 2; i++)
                areg[i] = a_ok ? *reinterpret_cast<const float4*>(
                                     &hin[(size_t)agrow * F + k1 + acol + i * 4])
                               : make_float4(0.f, 0.f, 0.f, 0.f);
        }
        asm volatile("cp.async.wait_group 0;");  // B chunk c landed
        __syncthreads();  // A stores + B visible; prior MMA reads done
        // cp.async B chunk c+1 into the other stage (overlaps MMA below)
        if (c < F / KT - 1) {
            const int k1 = (c + 1) * KT;
            CPA16(&sm[SBH(st ^ 1) + bn * LDP + bseg],
                  &g_Wh[(size_t)bn * F + k1 + bseg]);
            CPA16(&sm[SBH(st ^ 1) + bn * LDP + bseg + 8],
                  &g_Wh[(size_t)bn * F + k1 + bseg + 8]);
            asm volatile("cp.async.commit_group;");
        }

        // ---- MMA: 2 k-steps of 16; 4 ldmatrix + 16 HMMA each ----
#pragma unroll
        for (int ks = 0; ks < 2; ks++) {
            const int kb = ks * 16;
            uint32_t a[2][4];
#pragma unroll
            for (int mf = 0; mf < 2; mf++)
                LDMX4(a[mf], &sm[SA(st) + (wm + mf * 16 + ro) * LDP + kb + co]);
#pragma unroll
            for (int nt = 0; nt < 2; nt++) {
                uint32_t bh[4];
                int rb = (wn + nt * 16 + ro) * LDP + kb + co;
                LDMX4(bh, &sm[SBH(st) + rb]);
#pragma unroll
                for (int sl = 0; sl < 2; sl++) {
#pragma unroll
                    for (int mf = 0; mf < 2; mf++)
                        MMA_F16(d[mf][nt * 2 + sl], a[mf], bh[sl], bh[sl + 2]);
                }
            }
        }
        // no trailing sync: next iteration writes the other stage
    }

    // ---- epilogue: scale rows by rsqrt(deg_out), write fp16 ----
#pragma unroll
    for (int mf = 0; mf < 2; mf++) {
        int row0 = brow + wm + mf * 16 + g;
        int row1 = row0 + 8;
        float s0 = (row0 < n) ? rsqrtf((float)max(g_deg_out[row0], 1)) : 0.f;
        float s1 = (row1 < n) ? rsqrtf((float)max(g_deg_out[row1], 1)) : 0.f;
#pragma unroll
        for (int nf = 0; nf < 4; nf++) {
            int col = wn + nf * 8 + 2 * t;
            __half2 lo = __float22half2_rn(
                make_float2(d[mf][nf][0] * s0, d[mf][nf][1] * s0));
            __half2 hi = __float22half2_rn(
                make_float2(d[mf][nf][2] * s1, d[mf][nf][3] * s1));
            if (row0 < n)
                *reinterpret_cast<__half2*>(&g_x[(size_t)row0 * H + col]) = lo;
            if (row1 < n)
                *reinterpret_cast<__half2*>(&g_x[(size_t)row1 * H + col]) = hi;
        }
    }
}

// ---- fused CSR gather + in_norm + bias + LayerNorm: warp per node ----
// Same structure as the measured-good R8 version; only the unroll depth
// is raised 4 -> 8 to double outstanding-load parallelism.
__global__ __launch_bounds__(256) void gather_ln_kernel(
    const float* __restrict__ bias, const float* __restrict__ gamma,
    const float* __restrict__ beta, float* __restrict__ y, int n) {
    int node = blockIdx.x * 8 + (threadIdx.x >> 5);
    if (node >= n) return;
    int lane = threadIdx.x & 31;

    const int beg = g_off[node];
    const int cnt = g_deg_in[node];

    float4 acc = make_float4(0.f, 0.f, 0.f, 0.f);
    for (int base = 0; base < cnt; base += 32) {
        int m = min(32, cnt - base);
        int id = (lane < m) ? g_esrc[beg + base + lane] : 0;
#pragma unroll 8
        for (int j = 0; j < m; j++) {
            int sidx = __shfl_sync(0xffffffffu, id, j);
            uint2 raw = *reinterpret_cast<const uint2*>(
                &g_x[(size_t)sidx * H + lane * 4]);
            float2 f01 = __half22float2(*reinterpret_cast<__half2*>(&raw.x));
            float2 f23 = __half22float2(*reinterpret_cast<__half2*>(&raw.y));
            acc.x += f01.x; acc.y += f01.y; acc.z += f23.x; acc.w += f23.y;
        }
    }

    const float si = rsqrtf((float)max(cnt, 1));
    float4 bb = *reinterpret_cast<const float4*>(&bias[lane * 4]);
    float4 v;
    v.x = acc.x * si + bb.x;
    v.y = acc.y * si + bb.y;
    v.z = acc.z * si + bb.z;
    v.w = acc.w * si + bb.w;

    float sum = v.x + v.y + v.z + v.w;
#pragma unroll
    for (int o = 16; o; o >>= 1) sum += __shfl_xor_sync(0xffffffffu, sum, o);
    float mu = sum * (1.f / 128.f);

    float dx = v.x - mu, dy = v.y - mu, dz = v.z - mu, dw = v.w - mu;
    float sq = dx * dx + dy * dy + dz * dz + dw * dw;
#pragma unroll
    for (int o = 16; o; o >>= 1) sq += __shfl_xor_sync(0xffffffffu, sq, o);
    float rstd = rsqrtf(sq * (1.f / 128.f) + 1e-5f);

    float4 gm = *reinterpret_cast<const float4*>(&gamma[lane * 4]);
    float4 be = *reinterpret_cast<const float4*>(&beta[lane * 4]);
    float4 o4;
    o4.x = dx * rstd * gm.x + be.x;
    o4.y = dy * rstd * gm.y + be.y;
    o4.z = dz * rstd * gm.z + be.z;
    o4.w = dw * rstd * gm.w + be.w;
    *reinterpret_cast<float4*>(&y[(size_t)node * H + lane * 4]) = o4;
}

extern "C" void kernel_launch(void* const* d_in, const int* in_sizes, int n_in,
                              void* d_out, int out_size) {
    const float* h     = (const float*)d_in[0];
    const int*   src   = (const int*)d_in[1];
    const int*   dst   = (const int*)d_in[2];
    const float* W     = (const float*)d_in[3];
    const float* b     = (const float*)d_in[4];
    const float* gamma = (const float*)d_in[5];
    const float* beta  = (const float*)d_in[6];
    float* y = (float*)d_out;

    int n = in_sizes[0] / F;   // 50000
    int e = in_sizes[1];       // 800000

    static bool attr_set = false;
    if (!attr_set) {
        cudaFuncSetAttribute(gemm_mma_kernel,
                             cudaFuncAttributeMaxDynamicSharedMemorySize,
                             SM_BYTES);
        attr_set = true;
    }

    zero_kernel<<<(H * F + 255) / 256, 256>>>(W, n);            // 1
    deg_kernel<<<(e / 4 + 255) / 256, 256>>>(src, dst, e);      // 2
    gemm_mma_kernel<<<(n + 63) / 64, 256, SM_BYTES>>>(h, n);    // 3
    scan_kernel<<<(n + 255) / 256, 256>>>(n);                   // 4
    fill_kernel<<<(e / 4 + 255) / 256, 256>>>(src, dst, e);     // 5
    gather_ln_kernel<<<(n + 7) / 8, 256>>>(b, gamma, beta, y, n); // 6
}

// round 15
// speedup vs baseline: 1.1055x; 1.1055x over previous
#include <cuda_runtime.h>
#include <cuda_fp16.h>
#include <cstdint>

#define NMAX 50000
#define EMAX 800000
#define F 512
#define H 128

// ---- scratch (static device globals: no allocation allowed) ----
__device__ __half   g_x[(size_t)NMAX * H];     // (h @ W) * out_norm, fp16
__device__ int      g_deg_out[NMAX];
__device__ int      g_deg_in[NMAX];
__device__ int      g_off[NMAX];               // CSR offsets (by dst)
__device__ int      g_cursor[NMAX];            // fill cursors
__device__ int      g_esrc[EMAX];              // src ids grouped by dst
__device__ int      g_base_ctr;                // scan block-base counter
__device__ uint16_t g_Wh[(size_t)H * F];       // fp16 W^T: [n][k]

// ---- zero degrees + counter + W fp16 transpose (graph replays) ----
__global__ void zero_kernel(const float* __restrict__ W, int n) {
    int i = blockIdx.x * blockDim.x + threadIdx.x;
    if (i == 0) g_base_ctr = 0;
    if (i < n) { g_deg_out[i] = 0; g_deg_in[i] = 0; }
    if (i < H * F) {
        int nn = i >> 9;        // 0..127
        int k  = i & (F - 1);   // 0..511
        __half hv = __float2half_rn(W[(size_t)k * H + nn]);
        g_Wh[i] = *reinterpret_cast<uint16_t*>(&hv);
    }
}

// ---- out-degree histogram (src only; feeds gemm epilogue) ----
__global__ void deg_out_kernel(const int* __restrict__ src, int e) {
    int i4 = (blockIdx.x * blockDim.x + threadIdx.x) * 4;
    if (i4 + 3 < e) {
        int4 s = *reinterpret_cast<const int4*>(&src[i4]);
        atomicAdd(&g_deg_out[s.x], 1); atomicAdd(&g_deg_out[s.y], 1);
        atomicAdd(&g_deg_out[s.z], 1); atomicAdd(&g_deg_out[s.w], 1);
    } else {
        for (int i = i4; i < e; i++) atomicAdd(&g_deg_out[src[i]], 1);
    }
}

// ---- in-degree histogram (dst only; feeds scan/fill/gather) ----
__global__ void deg_in_kernel(const int* __restrict__ dst, int e) {
    int i4 = (blockIdx.x * blockDim.x + threadIdx.x) * 4;
    if (i4 + 3 < e) {
        int4 d = *reinterpret_cast<const int4*>(&dst[i4]);
        atomicAdd(&g_deg_in[d.x], 1);  atomicAdd(&g_deg_in[d.y], 1);
        atomicAdd(&g_deg_in[d.z], 1);  atomicAdd(&g_deg_in[d.w], 1);
    } else {
        for (int i = i4; i < e; i++) atomicAdd(&g_deg_in[dst[i]], 1);
    }
}

// ---- parallel exclusive scan: shfl warp scan, 2 barriers ----
__global__ __launch_bounds__(256) void scan_kernel(int n) {
    __shared__ int wsum[8];
    __shared__ int base;
    const int t = threadIdx.x;
    const int lane = t & 31;
    const int w = t >> 5;
    const int i = blockIdx.x * 256 + t;
    int d = (i < n) ? g_deg_in[i] : 0;

    int x = d;
#pragma unroll
    for (int off = 1; off < 32; off <<= 1) {
        int v = __shfl_up_sync(0xffffffffu, x, off);
        if (lane >= off) x += v;
    }
    if (lane == 31) wsum[w] = x;
    __syncthreads();
    if (w == 0) {
        int v = (lane < 8) ? wsum[lane] : 0;
#pragma unroll
        for (int off = 1; off < 8; off <<= 1) {
            int u = __shfl_up_sync(0xffffffffu, v, off);
            if (lane >= off) v += u;
        }
        if (lane < 8) wsum[lane] = v;
        if (lane == 7) base = atomicAdd(&g_base_ctr, v);
    }
    __syncthreads();
    if (i < n) {
        int o = base + (w ? wsum[w - 1] : 0) + x - d;
        g_off[i] = o;
        g_cursor[i] = o;
    }
}

// ---- CSR fill: group edge sources by destination (int4 vectorized) ----
__global__ void fill_kernel(const int* __restrict__ src,
                            const int* __restrict__ dst, int e) {
    int i4 = (blockIdx.x * blockDim.x + threadIdx.x) * 4;
    if (i4 + 3 < e) {
        int4 s = *reinterpret_cast<const int4*>(&src[i4]);
        int4 d = *reinterpret_cast<const int4*>(&dst[i4]);
        g_esrc[atomicAdd(&g_cursor[d.x], 1)] = s.x;
        g_esrc[atomicAdd(&g_cursor[d.y], 1)] = s.y;
        g_esrc[atomicAdd(&g_cursor[d.z], 1)] = s.z;
        g_esrc[atomicAdd(&g_cursor[d.w], 1)] = s.w;
    } else {
        for (int i = i4; i < e; i++)
            g_esrc[atomicAdd(&g_cursor[dst[i]], 1)] = src[i];
    }
}

// ============================================================
// Tensor-core GEMM v6 (measured 43.6us): single fp16 term,
// row-scale in epilogue:
//   g_x = (h @ W) * out_norm[:,None]   (out_norm = rsqrt(deg_out))
// CTA tile 64(m) x 128(n); 256 threads: 8 warps as 2(m) x 4(n),
// warp tile 32x32, 32 accum regs/thread -> 3 CTAs/SM.
// ============================================================
#define KT 32
#define LDP 40   // padded row length in halves (80B stride, ldmatrix-clean)
#define A_STG (64 * LDP)
#define B_STG (128 * LDP)

#define SA(st)  ((st) * A_STG)
#define SBH(st) (2 * A_STG + (st) * B_STG)
#define SM_HALVES (2 * A_STG + 2 * B_STG)
#define SM_BYTES (SM_HALVES * 2)   // 30720

#define MMA_F16(D, A, B0, B1)                                                \
    asm volatile(                                                            \
        "mma.sync.aligned.m16n8k16.row.col.f32.f16.f16.f32 "                 \
        "{%0,%1,%2,%3}, {%4,%5,%6,%7}, {%8,%9}, {%0,%1,%2,%3};"              \
        : "+f"((D)[0]), "+f"((D)[1]), "+f"((D)[2]), "+f"((D)[3])             \
        : "r"((A)[0]), "r"((A)[1]), "r"((A)[2]), "r"((A)[3]),                \
          "r"(B0), "r"(B1))

#define LDMX4(R, PTR)                                                        \
    do {                                                                     \
        uint32_t _a = (uint32_t)__cvta_generic_to_shared(PTR);               \
        asm volatile(                                                        \
            "ldmatrix.sync.aligned.m8n8.x4.shared.b16 {%0,%1,%2,%3}, [%4];"  \
            : "=r"((R)[0]), "=r"((R)[1]), "=r"((R)[2]), "=r"((R)[3])         \
            : "r"(_a));                                                      \
    } while (0)

#define CPA16(DST_PTR, SRC_PTR)                                              \
    do {                                                                     \
        uint32_t _d = (uint32_t)__cvta_generic_to_shared(DST_PTR);           \
        asm volatile("cp.async.cg.shared.global [%0], [%1], 16;"             \
                     :: "r"(_d), "l"(SRC_PTR));                              \
    } while (0)

__global__ __launch_bounds__(256, 3) void gemm_mma_kernel(
    const float* __restrict__ hin, int n) {
    extern __shared__ uint16_t sm[];
    const int tid = threadIdx.x;
    const int wid = tid >> 5;
    const int lid = tid & 31;
    const int g = lid >> 2;          // groupID
    const int t = lid & 3;           // threadID_in_group
    const int wm = (wid & 1) * 32;   // warp row base (2 m-tiles)
    const int wn = (wid >> 1) * 32;  // warp col base (4 n-tiles)
    const int brow = blockIdx.x * 64;
    const int ro = ((lid >> 3) & 1) * 8 + (lid & 7);
    const int co = (lid >> 4) * 8;

    float d[2][4][4];
#pragma unroll
    for (int mf = 0; mf < 2; mf++)
#pragma unroll
        for (int nf = 0; nf < 4; nf++)
#pragma unroll
            for (int q = 0; q < 4; q++) d[mf][nf][q] = 0.f;

    const int arow  = tid >> 2;
    const int acol  = (tid & 3) * 8;
    const int agrow = brow + arow;
    const bool a_ok = agrow < n;
    const int bn   = tid >> 1;
    const int bseg = (tid & 1) * 16;

    float4 areg[2];
#pragma unroll
    for (int i = 0; i < 2; i++)
        areg[i] = a_ok ? *reinterpret_cast<const float4*>(
                             &hin[(size_t)agrow * F + acol + i * 4])
                       : make_float4(0.f, 0.f, 0.f, 0.f);
    CPA16(&sm[SBH(0) + bn * LDP + bseg],     &g_Wh[(size_t)bn * F + bseg]);
    CPA16(&sm[SBH(0) + bn * LDP + bseg + 8], &g_Wh[(size_t)bn * F + bseg + 8]);
    asm volatile("cp.async.commit_group;");

    for (int c = 0; c < F / KT; c++) {
        const int st = c & 1;

#pragma unroll
        for (int i = 0; i < 2; i++) {
            __half2 p01 = __float22half2_rn(make_float2(areg[i].x, areg[i].y));
            __half2 p23 = __float22half2_rn(make_float2(areg[i].z, areg[i].w));
            uint2 hp;
            hp.x = *reinterpret_cast<uint32_t*>(&p01);
            hp.y = *reinterpret_cast<uint32_t*>(&p23);
            *reinterpret_cast<uint2*>(
                &sm[SA(st) + arow * LDP + acol + i * 4]) = hp;
        }
        if (c < F / KT - 1) {
            const int k1 = (c + 1) * KT;
#pragma unroll
            for (int i = 0; i < 2; i++)
                areg[i] = a_ok ? *reinterpret_cast<const float4*>(
                                     &hin[(size_t)agrow * F + k1 + acol + i * 4])
                               : make_float4(0.f, 0.f, 0.f, 0.f);
        }
        asm volatile("cp.async.wait_group 0;");
        __syncthreads();
        if (c < F / KT - 1) {
            const int k1 = (c + 1) * KT;
            CPA16(&sm[SBH(st ^ 1) + bn * LDP + bseg],
                  &g_Wh[(size_t)bn * F + k1 + bseg]);
            CPA16(&sm[SBH(st ^ 1) + bn * LDP + bseg + 8],
                  &g_Wh[(size_t)bn * F + k1 + bseg + 8]);
            asm volatile("cp.async.commit_group;");
        }

#pragma unroll
        for (int ks = 0; ks < 2; ks++) {
            const int kb = ks * 16;
            uint32_t a[2][4];
#pragma unroll
            for (int mf = 0; mf < 2; mf++)
                LDMX4(a[mf], &sm[SA(st) + (wm + mf * 16 + ro) * LDP + kb + co]);
#pragma unroll
            for (int nt = 0; nt < 2; nt++) {
                uint32_t bh[4];
                int rb = (wn + nt * 16 + ro) * LDP + kb + co;
                LDMX4(bh, &sm[SBH(st) + rb]);
#pragma unroll
                for (int sl = 0; sl < 2; sl++) {
#pragma unroll
                    for (int mf = 0; mf < 2; mf++)
                        MMA_F16(d[mf][nt * 2 + sl], a[mf], bh[sl], bh[sl + 2]);
                }
            }
        }
    }

#pragma unroll
    for (int mf = 0; mf < 2; mf++) {
        int row0 = brow + wm + mf * 16 + g;
        int row1 = row0 + 8;
        float s0 = (row0 < n) ? rsqrtf((float)max(g_deg_out[row0], 1)) : 0.f;
        float s1 = (row1 < n) ? rsqrtf((float)max(g_deg_out[row1], 1)) : 0.f;
#pragma unroll
        for (int nf = 0; nf < 4; nf++) {
            int col = wn + nf * 8 + 2 * t;
            __half2 lo = __float22half2_rn(
                make_float2(d[mf][nf][0] * s0, d[mf][nf][1] * s0));
            __half2 hi = __float22half2_rn(
                make_float2(d[mf][nf][2] * s1, d[mf][nf][3] * s1));
            if (row0 < n)
                *reinterpret_cast<__half2*>(&g_x[(size_t)row0 * H + col]) = lo;
            if (row1 < n)
                *reinterpret_cast<__half2*>(&g_x[(size_t)row1 * H + col]) = hi;
        }
    }
}

// ---- fused CSR gather + in_norm + bias + LayerNorm: warp per node ----
// (measured-best R8 version, unroll 4, verbatim)
__global__ __launch_bounds__(256) void gather_ln_kernel(
    const float* __restrict__ bias, const float* __restrict__ gamma,
    const float* __restrict__ beta, float* __restrict__ y, int n) {
    int node = blockIdx.x * 8 + (threadIdx.x >> 5);
    if (node >= n) return;
    int lane = threadIdx.x & 31;

    const int beg = g_off[node];
    const int cnt = g_deg_in[node];

    float4 acc = make_float4(0.f, 0.f, 0.f, 0.f);
    for (int base = 0; base < cnt; base += 32) {
        int m = min(32, cnt - base);
        int id = (lane < m) ? g_esrc[beg + base + lane] : 0;
#pragma unroll 4
        for (int j = 0; j < m; j++) {
            int sidx = __shfl_sync(0xffffffffu, id, j);
            uint2 raw = *reinterpret_cast<const uint2*>(
                &g_x[(size_t)sidx * H + lane * 4]);
            float2 f01 = __half22float2(*reinterpret_cast<__half2*>(&raw.x));
            float2 f23 = __half22float2(*reinterpret_cast<__half2*>(&raw.y));
            acc.x += f01.x; acc.y += f01.y; acc.z += f23.x; acc.w += f23.y;
        }
    }

    const float si = rsqrtf((float)max(cnt, 1));
    float4 bb = *reinterpret_cast<const float4*>(&bias[lane * 4]);
    float4 v;
    v.x = acc.x * si + bb.x;
    v.y = acc.y * si + bb.y;
    v.z = acc.z * si + bb.z;
    v.w = acc.w * si + bb.w;

    float sum = v.x + v.y + v.z + v.w;
#pragma unroll
    for (int o = 16; o; o >>= 1) sum += __shfl_xor_sync(0xffffffffu, sum, o);
    float mu = sum * (1.f / 128.f);

    float dx = v.x - mu, dy = v.y - mu, dz = v.z - mu, dw = v.w - mu;
    float sq = dx * dx + dy * dy + dz * dz + dw * dw;
#pragma unroll
    for (int o = 16; o; o >>= 1) sq += __shfl_xor_sync(0xffffffffu, sq, o);
    float rstd = rsqrtf(sq * (1.f / 128.f) + 1e-5f);

    float4 gm = *reinterpret_cast<const float4*>(&gamma[lane * 4]);
    float4 be = *reinterpret_cast<const float4*>(&beta[lane * 4]);
    float4 o4;
    o4.x = dx * rstd * gm.x + be.x;
    o4.y = dy * rstd * gm.y + be.y;
    o4.z = dz * rstd * gm.z + be.z;
    o4.w = dw * rstd * gm.w + be.w;
    *reinterpret_cast<float4*>(&y[(size_t)node * H + lane * 4]) = o4;
}

extern "C" void kernel_launch(void* const* d_in, const int* in_sizes, int n_in,
                              void* d_out, int out_size) {
    const float* h     = (const float*)d_in[0];
    const int*   src   = (const int*)d_in[1];
    const int*   dst   = (const int*)d_in[2];
    const float* W     = (const float*)d_in[3];
    const float* b     = (const float*)d_in[4];
    const float* gamma = (const float*)d_in[5];
    const float* beta  = (const float*)d_in[6];
    float* y = (float*)d_out;

    int n = in_sizes[0] / F;   // 50000
    int e = in_sizes[1];       // 800000

    static cudaStream_t s2 = nullptr;
    static cudaEvent_t evF = nullptr, evJ = nullptr;
    if (!s2) {
        cudaStreamCreateWithFlags(&s2, cudaStreamNonBlocking);
        cudaEventCreateWithFlags(&evF, cudaEventDisableTiming);
        cudaEventCreateWithFlags(&evJ, cudaEventDisableTiming);
        cudaFuncSetAttribute(gemm_mma_kernel,
                             cudaFuncAttributeMaxDynamicSharedMemorySize,
                             SM_BYTES);
    }

    // main stream: zero -> deg_out -> gemm
    zero_kernel<<<(H * F + 255) / 256, 256>>>(W, n);
    cudaEventRecord(evF, 0);
    // side stream: deg_in -> scan -> fill (CSR build, overlaps gemm)
    cudaStreamWaitEvent(s2, evF, 0);
    deg_in_kernel<<<(e / 4 + 255) / 256, 256, 0, s2>>>(dst, e);
    scan_kernel<<<(n + 255) / 256, 256, 0, s2>>>(n);
    fill_kernel<<<(e / 4 + 255) / 256, 256, 0, s2>>>(src, dst, e);
    cudaEventRecord(evJ, s2);

    deg_out_kernel<<<(e / 4 + 255) / 256, 256>>>(src, e);
    gemm_mma_kernel<<<(n + 63) / 64, 256, SM_BYTES>>>(h, n);

    // join: gather needs gemm (g_x), CSR (g_off/g_esrc), deg_in
    cudaStreamWaitEvent(0, evJ, 0);
    gather_ln_kernel<<<(n + 7) / 8, 256>>>(b, gamma, beta, y, n);
}